// round 5
// baseline (speedup 1.0000x reference)
#include <cuda_runtime.h>
#include <math.h>

#define NN   4096
#define RTOT 501
#define RPAD 512
#define NLEV 5

// ---- device scratch (static allocation: allowed) ----
__device__ float g_Wc[NN * RPAD];   // phi/psi factors for xc (rows) : [n][r]
__device__ float g_Wr[NN * RPAD];   // factors for xr (cols)         : [m][r]
__device__ float g_T [NN * RPAD];   // T = Wc * blockdiag(D)         : [n][r]
__device__ int   g_ic[RTOT];
__device__ int   g_ir[RTOT];
__device__ float g_D [257 * 257];   // current level's D

// ---------------------------------------------------------------------------
// phi(a) = sin(pi a) * exp(-a^2 / (2*3.2^2)) / (pi a),  phi(0)=1
// ---------------------------------------------------------------------------
__device__ __forceinline__ float phi_f(float a) {
    float t = 3.14159265358979323846f * a;
    if (t == 0.0f) return 1.0f;
    return sinf(t) * expf(-(a * a) / 20.48f) / t;
}

// col -> (level offset, scale); levels: off={0,17,50,115,244}, s={8,16,32,64,128}
__device__ __forceinline__ void col_to_level(int col, int& off, int& s) {
    if (col < 17)       { off = 0;   s = 8;   }
    else if (col < 50)  { off = 17;  s = 16;  }
    else if (col < 115) { off = 50;  s = 32;  }
    else if (col < 244) { off = 115; s = 64;  }
    else                { off = 244; s = 128; }
}

// ---------------------------------------------------------------------------
// Fill Wc, Wr (and zero the pad columns of Wc, Wr, T)
// ---------------------------------------------------------------------------
__global__ void k_compute_w(const float* __restrict__ xc,
                            const float* __restrict__ xr) {
    int idx = blockIdx.x * blockDim.x + threadIdx.x;
    if (idx >= NN * RPAD) return;
    int n   = idx >> 9;       // / RPAD
    int col = idx & (RPAD - 1);
    if (col >= RTOT) {
        g_Wc[idx] = 0.0f; g_Wr[idx] = 0.0f; g_T[idx] = 0.0f;
        return;
    }
    int off, s;
    col_to_level(col, off, s);
    int m = (col - off) - s;            // integer grid position -s..s
    float fs = (float)s, fm = (float)m;
    g_Wc[idx] = phi_f(fs * xc[n] - fm);
    g_Wr[idx] = phi_f(fs * xr[n] - fm);
}

// ---------------------------------------------------------------------------
// nearest index into sorted x for each grid target xjk = m/s
// (argmin of |x - target|, first index on ties -> lower index)
// ---------------------------------------------------------------------------
__device__ __forceinline__ int nearest_sorted(const float* __restrict__ x, float tgt) {
    int lo = 0, hi = NN;
    while (lo < hi) { int mid = (lo + hi) >> 1; if (x[mid] < tgt) lo = mid + 1; else hi = mid; }
    if (lo == 0)  return 0;
    if (lo == NN) return NN - 1;
    float d1 = fabsf(x[lo - 1] - tgt);
    float d2 = fabsf(x[lo] - tgt);
    return (d1 <= d2) ? (lo - 1) : lo;
}

__global__ void k_compute_idx(const float* __restrict__ xc,
                              const float* __restrict__ xr) {
    int col = blockIdx.x * blockDim.x + threadIdx.x;
    if (col >= RTOT) return;
    int off, s;
    col_to_level(col, off, s);
    int m = (col - off) - s;
    float tgt = (float)m / (float)s;   // exact (power-of-two denominator)
    g_ic[col] = nearest_sorted(xc, tgt);
    g_ir[col] = nearest_sorted(xr, tgt);
}

// ---------------------------------------------------------------------------
// D_l[a,b] = thresh( img[ic_a, ir_b] - U[a,b] ),
// U[a,b] = sum_{r<off} T[ic_a, r] * Wr[ir_b, r]     (level 0: U=0, no thresh)
// grid: (ceil(K/256), K) ; block: 256 (b dimension)
// ---------------------------------------------------------------------------
__global__ void k_compute_D(const float* __restrict__ img,
                            int off, int K, int thresh_on) {
    __shared__ float Trow[256];
    int a   = blockIdx.y;
    int b   = blockIdx.x * blockDim.x + threadIdx.x;
    int ica = g_ic[off + a];
    for (int r = threadIdx.x; r < off; r += blockDim.x)
        Trow[r] = g_T[(size_t)ica * RPAD + r];
    __syncthreads();
    if (b >= K) return;
    int irb = g_ir[off + b];
    const float* wr = &g_Wr[(size_t)irb * RPAD];
    float u = 0.0f;
    for (int r = 0; r < off; ++r) u += Trow[r] * wr[r];
    float d = img[(size_t)ica * NN + irb] - u;
    if (thresh_on && fabsf(d) <= 0.01f) d = 0.0f;
    g_D[a * K + b] = d;
}

// ---------------------------------------------------------------------------
// T[:, off+b] = sum_a Wc[:, off+a] * D[a,b]
// block (64,4): x over b (coalesced D reads), y over n
// ---------------------------------------------------------------------------
__global__ void k_compute_T(int off, int K) {
    int b = blockIdx.x * blockDim.x + threadIdx.x;
    int n = blockIdx.y * blockDim.y + threadIdx.y;
    if (b >= K) return;
    const float* wc = &g_Wc[(size_t)n * RPAD + off];
    float acc = 0.0f;
    for (int a = 0; a < K; ++a)
        acc += wc[a] * g_D[a * K + b];
    g_T[(size_t)n * RPAD + off + b] = acc;
}

// ---------------------------------------------------------------------------
// out[n,m] = sum_{k<512} T[n,k] * Wr[m,k]        (pad cols are zero)
// 128x128x16 tiles, 256 threads, 8x8 micro-tiles
// ---------------------------------------------------------------------------
#define BM 128
#define BN 128
#define BK 16

__global__ __launch_bounds__(256) void k_gemm(float* __restrict__ C) {
    __shared__ float Ts[BK][BM + 4];
    __shared__ float Ws[BK][BN + 4];

    const int tid = threadIdx.x;
    const int n0  = blockIdx.y * BM;
    const int m0  = blockIdx.x * BN;
    const int lr  = tid >> 2;           // 0..63  (tile row for loads)
    const int lc  = (tid & 3) << 2;     // 0,4,8,12 (k offset for loads)
    const int ty  = tid >> 4;           // 0..15 -> n micro-tile
    const int tx  = tid & 15;           // 0..15 -> m micro-tile

    float acc[8][8];
#pragma unroll
    for (int i = 0; i < 8; ++i)
#pragma unroll
        for (int j = 0; j < 8; ++j) acc[i][j] = 0.0f;

    const float* Ag = g_T  + (size_t)(n0 + lr) * RPAD + lc;
    const float* Bg = g_Wr + (size_t)(m0 + lr) * RPAD + lc;

    for (int k0 = 0; k0 < RPAD; k0 += BK) {
        float4 a0 = *(const float4*)(Ag + k0);
        float4 a1 = *(const float4*)(Ag + k0 + (size_t)64 * RPAD);
        float4 b0 = *(const float4*)(Bg + k0);
        float4 b1 = *(const float4*)(Bg + k0 + (size_t)64 * RPAD);

        __syncthreads();   // previous iteration's compute done
        Ts[lc + 0][lr]      = a0.x; Ts[lc + 1][lr]      = a0.y;
        Ts[lc + 2][lr]      = a0.z; Ts[lc + 3][lr]      = a0.w;
        Ts[lc + 0][lr + 64] = a1.x; Ts[lc + 1][lr + 64] = a1.y;
        Ts[lc + 2][lr + 64] = a1.z; Ts[lc + 3][lr + 64] = a1.w;
        Ws[lc + 0][lr]      = b0.x; Ws[lc + 1][lr]      = b0.y;
        Ws[lc + 2][lr]      = b0.z; Ws[lc + 3][lr]      = b0.w;
        Ws[lc + 0][lr + 64] = b1.x; Ws[lc + 1][lr + 64] = b1.y;
        Ws[lc + 2][lr + 64] = b1.z; Ws[lc + 3][lr + 64] = b1.w;
        __syncthreads();

#pragma unroll
        for (int kk = 0; kk < BK; ++kk) {
            float ar[8], br[8];
#pragma unroll
            for (int i = 0; i < 8; ++i) ar[i] = Ts[kk][ty * 8 + i];
#pragma unroll
            for (int j = 0; j < 8; ++j) br[j] = Ws[kk][tx * 8 + j];
#pragma unroll
            for (int i = 0; i < 8; ++i)
#pragma unroll
                for (int j = 0; j < 8; ++j)
                    acc[i][j] = fmaf(ar[i], br[j], acc[i][j]);
        }
    }

#pragma unroll
    for (int i = 0; i < 8; ++i) {
        int n = n0 + ty * 8 + i;
        float4* cp = (float4*)(C + (size_t)n * NN + m0 + tx * 8);
        cp[0] = make_float4(acc[i][0], acc[i][1], acc[i][2], acc[i][3]);
        cp[1] = make_float4(acc[i][4], acc[i][5], acc[i][6], acc[i][7]);
    }
}

// ---------------------------------------------------------------------------
extern "C" void kernel_launch(void* const* d_in, const int* in_sizes, int n_in,
                              void* d_out, int out_size) {
    const float* img = (const float*)d_in[0];
    const float* xc  = (const float*)d_in[1];
    const float* xr  = (const float*)d_in[2];
    float* out = (float*)d_out;

    (void)in_sizes; (void)n_in; (void)out_size;

    // 1. factors
    k_compute_w<<<(NN * RPAD) / 256, 256>>>(xc, xr);
    // 2. nearest indices
    k_compute_idx<<<2, 256>>>(xc, xr);

    // 3. per-level D and T blocks (sequential: U depends on previous T)
    static const int offs[NLEV] = {0, 17, 50, 115, 244};
    static const int Ks[NLEV]   = {17, 33, 65, 129, 257};
    for (int l = 0; l < NLEV; ++l) {
        dim3 gD((Ks[l] + 255) / 256, Ks[l]);
        k_compute_D<<<gD, 256>>>(img, offs[l], Ks[l], l > 0 ? 1 : 0);
        dim3 bT(64, 4), gT((Ks[l] + 63) / 64, NN / 4);
        k_compute_T<<<gT, bT>>>(offs[l], Ks[l]);
    }

    // 4. out = T * Wr^T  (single dense GEMM, K padded to 512 with zeros)
    dim3 gg(NN / BN, NN / BM);
    k_gemm<<<gg, 256>>>(out);
}

// round 7
// speedup vs baseline: 1.5768x; 1.5768x over previous
#include <cuda_runtime.h>
#include <cuda_bf16.h>
#include <math.h>
#include <stdint.h>

#define NN   4096
#define RTOT 501
#define RPAD 512
#define NLEV 5

// ---- device scratch (static allocation: allowed) ----
__device__ float g_Wc[NN * RPAD];   // phi/psi factors for xc (rows) : [n][r]
__device__ float g_Wr[NN * RPAD];   // factors for xr (cols)         : [m][r]
__device__ float g_T [NN * RPAD];   // T = Wc * blockdiag(D)         : [n][r]
__device__ int   g_ic[RTOT];
__device__ int   g_ir[RTOT];
__device__ float g_D [257 * 257];   // current level's D
// bf16 split operands for the tensor-core GEMM
__device__ __align__(1024) __nv_bfloat16 g_Ahi[NN * RPAD];
__device__ __align__(1024) __nv_bfloat16 g_Alo[NN * RPAD];
__device__ __align__(1024) __nv_bfloat16 g_Bhi[NN * RPAD];
__device__ __align__(1024) __nv_bfloat16 g_Blo[NN * RPAD];

// ---------------------------------------------------------------------------
__device__ __forceinline__ float phi_f(float a) {
    float t = 3.14159265358979323846f * a;
    if (t == 0.0f) return 1.0f;
    return sinf(t) * expf(-(a * a) / 20.48f) / t;
}

__device__ __forceinline__ void col_to_level(int col, int& off, int& s) {
    if (col < 17)       { off = 0;   s = 8;   }
    else if (col < 50)  { off = 17;  s = 16;  }
    else if (col < 115) { off = 50;  s = 32;  }
    else if (col < 244) { off = 115; s = 64;  }
    else                { off = 244; s = 128; }
}

__global__ void k_compute_w(const float* __restrict__ xc,
                            const float* __restrict__ xr) {
    int idx = blockIdx.x * blockDim.x + threadIdx.x;
    if (idx >= NN * RPAD) return;
    int n   = idx >> 9;
    int col = idx & (RPAD - 1);
    if (col >= RTOT) {
        g_Wc[idx] = 0.0f; g_Wr[idx] = 0.0f; g_T[idx] = 0.0f;
        return;
    }
    int off, s;
    col_to_level(col, off, s);
    int m = (col - off) - s;
    float fs = (float)s, fm = (float)m;
    g_Wc[idx] = phi_f(fs * xc[n] - fm);
    g_Wr[idx] = phi_f(fs * xr[n] - fm);
}

__device__ __forceinline__ int nearest_sorted(const float* __restrict__ x, float tgt) {
    int lo = 0, hi = NN;
    while (lo < hi) { int mid = (lo + hi) >> 1; if (x[mid] < tgt) lo = mid + 1; else hi = mid; }
    if (lo == 0)  return 0;
    if (lo == NN) return NN - 1;
    float d1 = fabsf(x[lo - 1] - tgt);
    float d2 = fabsf(x[lo] - tgt);
    return (d1 <= d2) ? (lo - 1) : lo;
}

__global__ void k_compute_idx(const float* __restrict__ xc,
                              const float* __restrict__ xr) {
    int col = blockIdx.x * blockDim.x + threadIdx.x;
    if (col >= RTOT) return;
    int off, s;
    col_to_level(col, off, s);
    int m = (col - off) - s;
    float tgt = (float)m / (float)s;
    g_ic[col] = nearest_sorted(xc, tgt);
    g_ir[col] = nearest_sorted(xr, tgt);
}

__global__ void k_compute_D(const float* __restrict__ img,
                            int off, int K, int thresh_on) {
    __shared__ float Trow[256];
    int a   = blockIdx.y;
    int b   = blockIdx.x * blockDim.x + threadIdx.x;
    int ica = g_ic[off + a];
    for (int r = threadIdx.x; r < off; r += blockDim.x)
        Trow[r] = g_T[(size_t)ica * RPAD + r];
    __syncthreads();
    if (b >= K) return;
    int irb = g_ir[off + b];
    const float* wr = &g_Wr[(size_t)irb * RPAD];
    float u = 0.0f;
    for (int r = 0; r < off; ++r) u += Trow[r] * wr[r];
    float d = img[(size_t)ica * NN + irb] - u;
    if (thresh_on && fabsf(d) <= 0.01f) d = 0.0f;
    g_D[a * K + b] = d;
}

__global__ void k_compute_T(int off, int K) {
    int b = blockIdx.x * blockDim.x + threadIdx.x;
    int n = blockIdx.y * blockDim.y + threadIdx.y;
    if (b >= K) return;
    const float* wc = &g_Wc[(size_t)n * RPAD + off];
    float acc = 0.0f;
    for (int a = 0; a < K; ++a)
        acc += wc[a] * g_D[a * K + b];
    g_T[(size_t)n * RPAD + off + b] = acc;
}

// ---------------------------------------------------------------------------
// Split fp32 -> bf16 hi/lo for both GEMM operands (pad cols are zero -> zero)
// ---------------------------------------------------------------------------
__global__ void k_split() {
    int idx = blockIdx.x * blockDim.x + threadIdx.x;
    float a = g_T[idx];
    __nv_bfloat16 ha = __float2bfloat16(a);
    g_Ahi[idx] = ha;
    g_Alo[idx] = __float2bfloat16(a - __bfloat162float(ha));
    float b = g_Wr[idx];
    __nv_bfloat16 hb = __float2bfloat16(b);
    g_Bhi[idx] = hb;
    g_Blo[idx] = __float2bfloat16(b - __bfloat162float(hb));
}

// ---------------------------------------------------------------------------
// Tensor-core GEMM via mma.sync (HMMA path — valid under compute_103):
//   C[4096x4096] = T * Wr^T, 3-pass bf16 split folded into 24 K-chunks.
// CTA tile 128x128, BK=64 bf16 (128B rows, SW128 xor swizzle), 8 warps
// (2x4), warp tile 64x32, m16n8k16 fragments via ldmatrix.x4.
// Double-buffered cp.async stages.
// ---------------------------------------------------------------------------
#define SWZ(o) ((o) ^ (((o) >> 3) & 0x70))
#define STAGEB 32768                  // A 16K + B 16K
#define GSMEM  (2 * STAGEB)
#define NCHUNK 24                     // 3 passes x 8 chunks of K=64

__device__ __forceinline__ uint32_t smem_u32(const void* p) {
    uint32_t a;
    asm("{ .reg .u64 t; cvta.to.shared.u64 t, %1; cvt.u32.u64 %0, t; }"
        : "=r"(a) : "l"(p));
    return a;
}
__device__ __forceinline__ void cp16(uint32_t s, const void* g) {
    asm volatile("cp.async.cg.shared.global [%0], [%1], 16;" :: "r"(s), "l"(g));
}
__device__ __forceinline__ void ldm_x4(uint32_t& r0, uint32_t& r1,
                                       uint32_t& r2, uint32_t& r3, uint32_t a) {
    asm volatile("ldmatrix.sync.aligned.m8n8.x4.shared.b16 {%0,%1,%2,%3}, [%4];"
                 : "=r"(r0), "=r"(r1), "=r"(r2), "=r"(r3) : "r"(a));
}
__device__ __forceinline__ void mma_bf16(float& d0, float& d1, float& d2, float& d3,
                                         uint32_t a0, uint32_t a1, uint32_t a2,
                                         uint32_t a3, uint32_t b0, uint32_t b1) {
    asm volatile(
        "mma.sync.aligned.m16n8k16.row.col.f32.bf16.bf16.f32 "
        "{%0,%1,%2,%3}, {%4,%5,%6,%7}, {%8,%9}, {%0,%1,%2,%3};"
        : "+f"(d0), "+f"(d1), "+f"(d2), "+f"(d3)
        : "r"(a0), "r"(a1), "r"(a2), "r"(a3), "r"(b0), "r"(b1));
}

__global__ __launch_bounds__(256, 2) void k_gemm_mma(float* __restrict__ C) {
    extern __shared__ char smem[];
    const uint32_t sb = smem_u32(smem);
    const int tid  = threadIdx.x;
    const int wid  = tid >> 5, lane = tid & 31;
    const int n0   = blockIdx.y * 128;   // C rows  (A = T rows)
    const int m0   = blockIdx.x * 128;   // C cols  (B = Wr rows)
    const int wm   = (wid >> 2) * 64;    // warp row offset in tile
    const int wn   = (wid & 3) * 32;     // warp col offset in tile

    const __nv_bfloat16* APs[3] = { g_Ahi, g_Ahi, g_Alo };
    const __nv_bfloat16* BPs[3] = { g_Bhi, g_Blo, g_Bhi };

    float acc[4][4][4];
#pragma unroll
    for (int i = 0; i < 4; ++i)
#pragma unroll
        for (int j = 0; j < 4; ++j)
#pragma unroll
            for (int q = 0; q < 4; ++q) acc[i][j][q] = 0.0f;

    // cp.async load of one (A,B) 128x64 bf16 chunk pair into a stage
    auto load_chunk = [&](int c, int stage) {
        const int pass = c / 8, k0 = (c & 7) * 64;
        const __nv_bfloat16* Ag = APs[pass];
        const __nv_bfloat16* Bg = BPs[pass];
        const uint32_t sA = sb + stage * STAGEB;
        const uint32_t sBq = sA + 16384;
#pragma unroll
        for (int i = 0; i < 4; ++i) {           // 1024 16B units, 256 thr
            int u = tid + i * 256;
            int row = u >> 3, cq = u & 7;       // cq: 16B chunk in row
            uint32_t so = SWZ(row * 128 + cq * 16);
            cp16(sA + so,  Ag + (size_t)(n0 + row) * RPAD + k0 + cq * 8);
            cp16(sBq + so, Bg + (size_t)(m0 + row) * RPAD + k0 + cq * 8);
        }
        asm volatile("cp.async.commit_group;" ::: "memory");
    };

    load_chunk(0, 0);
    load_chunk(1, 1);

    for (int c = 0; c < NCHUNK; ++c) {
        const int stage = c & 1;
        if (c < NCHUNK - 1) asm volatile("cp.async.wait_group 1;" ::: "memory");
        else                asm volatile("cp.async.wait_group 0;" ::: "memory");
        __syncthreads();

        const uint32_t sA = sb + stage * STAGEB;
        const uint32_t sBq = sA + 16384;

#pragma unroll
        for (int ks = 0; ks < 4; ++ks) {        // k16 steps within BK=64
            uint32_t a[4][4];
#pragma unroll
            for (int mi = 0; mi < 4; ++mi) {
                int r  = wm + mi * 16 + (lane & 15);
                int cb = (ks * 2 + (lane >> 4)) * 16;
                ldm_x4(a[mi][0], a[mi][1], a[mi][2], a[mi][3],
                       sA + SWZ(r * 128 + cb));
            }
            uint32_t b[2][4];
#pragma unroll
            for (int nq = 0; nq < 2; ++nq) {
                int r  = wn + nq * 16 + ((lane >> 4) & 1) * 8 + (lane & 7);
                int cb = (ks * 2 + ((lane >> 3) & 1)) * 16;
                ldm_x4(b[nq][0], b[nq][1], b[nq][2], b[nq][3],
                       sBq + SWZ(r * 128 + cb));
            }
#pragma unroll
            for (int mi = 0; mi < 4; ++mi)
#pragma unroll
                for (int nj = 0; nj < 4; ++nj) {
                    int nq = nj >> 1, nb = nj & 1;
                    mma_bf16(acc[mi][nj][0], acc[mi][nj][1],
                             acc[mi][nj][2], acc[mi][nj][3],
                             a[mi][0], a[mi][1], a[mi][2], a[mi][3],
                             b[nq][2 * nb], b[nq][2 * nb + 1]);
                }
        }

        __syncthreads();                        // all reads of this stage done
        if (c + 2 < NCHUNK) load_chunk(c + 2, stage);
    }

    // Epilogue: thread (lane) holds c0,c1 @ (row, col..col+1), c2,c3 @ row+8
#pragma unroll
    for (int mi = 0; mi < 4; ++mi) {
        int row = n0 + wm + mi * 16 + (lane >> 2);
#pragma unroll
        for (int nj = 0; nj < 4; ++nj) {
            int col = m0 + wn + nj * 8 + (lane & 3) * 2;
            float2* p0 = (float2*)(C + (size_t)row * NN + col);
            float2* p1 = (float2*)(C + (size_t)(row + 8) * NN + col);
            *p0 = make_float2(acc[mi][nj][0], acc[mi][nj][1]);
            *p1 = make_float2(acc[mi][nj][2], acc[mi][nj][3]);
        }
    }
}

// ---------------------------------------------------------------------------
extern "C" void kernel_launch(void* const* d_in, const int* in_sizes, int n_in,
                              void* d_out, int out_size) {
    const float* img = (const float*)d_in[0];
    const float* xc  = (const float*)d_in[1];
    const float* xr  = (const float*)d_in[2];
    float* out = (float*)d_out;

    (void)in_sizes; (void)n_in; (void)out_size;

    cudaFuncSetAttribute(k_gemm_mma, cudaFuncAttributeMaxDynamicSharedMemorySize,
                         GSMEM);

    // 1. factors
    k_compute_w<<<(NN * RPAD) / 256, 256>>>(xc, xr);
    // 2. nearest indices
    k_compute_idx<<<2, 256>>>(xc, xr);

    // 3. per-level D and T blocks (sequential: U depends on previous T)
    static const int offs[NLEV] = {0, 17, 50, 115, 244};
    static const int Ks[NLEV]   = {17, 33, 65, 129, 257};
    for (int l = 0; l < NLEV; ++l) {
        dim3 gD((Ks[l] + 255) / 256, Ks[l]);
        k_compute_D<<<gD, 256>>>(img, offs[l], Ks[l], l > 0 ? 1 : 0);
        dim3 bT(64, 4), gT((Ks[l] + 63) / 64, NN / 4);
        k_compute_T<<<gT, bT>>>(offs[l], Ks[l]);
    }

    // 4. bf16 hi/lo split of T and Wr
    k_split<<<(NN * RPAD) / 256, 256>>>();

    // 5. out = T * Wr^T on tensor cores (3-pass bf16 split, fp32 accumulate)
    dim3 gg(NN / 128, NN / 128);   // (32, 32)
    k_gemm_mma<<<gg, 256, GSMEM>>>(out);
}

// round 8
// speedup vs baseline: 1.6124x; 1.0226x over previous
#include <cuda_runtime.h>
#include <cuda_bf16.h>
#include <math.h>
#include <stdint.h>

#define NN   4096
#define RTOT 501
#define RPAD 512
#define NLEV 5

// ---- device scratch (static allocation: allowed) ----
__device__ float g_Wc[NN * RPAD];   // phi/psi factors for xc (rows) : [n][r]
__device__ float g_Wr[NN * RPAD];   // factors for xr (cols)         : [m][r]
__device__ float g_T [NN * RPAD];   // T = Wc * blockdiag(D)         : [n][r]
__device__ int   g_ic[RTOT];
__device__ int   g_ir[RTOT];
__device__ float g_D [257 * 257];   // current level's D
// bf16 split operands for the tensor-core GEMM
__device__ __align__(1024) __nv_bfloat16 g_Ahi[NN * RPAD];
__device__ __align__(1024) __nv_bfloat16 g_Alo[NN * RPAD];
__device__ __align__(1024) __nv_bfloat16 g_Bhi[NN * RPAD];
__device__ __align__(1024) __nv_bfloat16 g_Blo[NN * RPAD];

// ---------------------------------------------------------------------------
// phi(a) = sin(pi a) * exp(-a^2/20.48) / (pi a), phi(0)=1.
// Fast path: sinpif (cheap reduction), __expf, __fdividef (1 MUFU each),
// and a cutoff: |a|>28 -> exp factor < 2e-17 -> contribution below fp32 noise.
// ---------------------------------------------------------------------------
__device__ __forceinline__ float phi_f(float a) {
    float t = 3.14159265358979323846f * a;
    if (t == 0.0f) return 1.0f;
    float a2 = a * a;
    if (a2 > 784.0f) return 0.0f;
    return __fdividef(sinpif(a), t) * __expf(a2 * (-1.0f / 20.48f));
}

__device__ __forceinline__ void col_to_level(int col, int& off, int& s) {
    if (col < 17)       { off = 0;   s = 8;   }
    else if (col < 50)  { off = 17;  s = 16;  }
    else if (col < 115) { off = 50;  s = 32;  }
    else if (col < 244) { off = 115; s = 64;  }
    else                { off = 244; s = 128; }
}

__global__ void k_compute_w(const float* __restrict__ xc,
                            const float* __restrict__ xr) {
    int idx = blockIdx.x * blockDim.x + threadIdx.x;
    if (idx >= NN * RPAD) return;
    int n   = idx >> 9;
    int col = idx & (RPAD - 1);
    if (col >= RTOT) {
        g_Wc[idx] = 0.0f; g_Wr[idx] = 0.0f; g_T[idx] = 0.0f;
        return;
    }
    int off, s;
    col_to_level(col, off, s);
    int m = (col - off) - s;
    float fs = (float)s, fm = (float)m;
    g_Wc[idx] = phi_f(fs * xc[n] - fm);
    g_Wr[idx] = phi_f(fs * xr[n] - fm);
}

__device__ __forceinline__ int nearest_sorted(const float* __restrict__ x, float tgt) {
    int lo = 0, hi = NN;
    while (lo < hi) { int mid = (lo + hi) >> 1; if (x[mid] < tgt) lo = mid + 1; else hi = mid; }
    if (lo == 0)  return 0;
    if (lo == NN) return NN - 1;
    float d1 = fabsf(x[lo - 1] - tgt);
    float d2 = fabsf(x[lo] - tgt);
    return (d1 <= d2) ? (lo - 1) : lo;
}

__global__ void k_compute_idx(const float* __restrict__ xc,
                              const float* __restrict__ xr) {
    int col = blockIdx.x * blockDim.x + threadIdx.x;
    if (col >= RTOT) return;
    int off, s;
    col_to_level(col, off, s);
    int m = (col - off) - s;
    float tgt = (float)m / (float)s;
    g_ic[col] = nearest_sorted(xc, tgt);
    g_ir[col] = nearest_sorted(xr, tgt);
}

__global__ void k_compute_D(const float* __restrict__ img,
                            int off, int K, int thresh_on) {
    __shared__ float Trow[256];
    int a   = blockIdx.y;
    int b   = blockIdx.x * blockDim.x + threadIdx.x;
    int ica = g_ic[off + a];
    for (int r = threadIdx.x; r < off; r += blockDim.x)
        Trow[r] = g_T[(size_t)ica * RPAD + r];
    __syncthreads();
    if (b >= K) return;
    int irb = g_ir[off + b];
    const float* wr = &g_Wr[(size_t)irb * RPAD];
    float u = 0.0f;
    for (int r = 0; r < off; ++r) u += Trow[r] * wr[r];
    float d = img[(size_t)ica * NN + irb] - u;
    if (thresh_on && fabsf(d) <= 0.01f) d = 0.0f;
    g_D[a * K + b] = d;
}

__global__ void k_compute_T(int off, int K) {
    int b = blockIdx.x * blockDim.x + threadIdx.x;
    int n = blockIdx.y * blockDim.y + threadIdx.y;
    if (b >= K) return;
    const float* wc = &g_Wc[(size_t)n * RPAD + off];
    float acc = 0.0f;
    for (int a = 0; a < K; ++a)
        acc += wc[a] * g_D[a * K + b];
    g_T[(size_t)n * RPAD + off + b] = acc;
}

// ---------------------------------------------------------------------------
// Split fp32 -> bf16 hi/lo for both GEMM operands (pad cols are zero -> zero)
// ---------------------------------------------------------------------------
__global__ void k_split() {
    int idx = blockIdx.x * blockDim.x + threadIdx.x;
    float a = g_T[idx];
    __nv_bfloat16 ha = __float2bfloat16(a);
    g_Ahi[idx] = ha;
    g_Alo[idx] = __float2bfloat16(a - __bfloat162float(ha));
    float b = g_Wr[idx];
    __nv_bfloat16 hb = __float2bfloat16(b);
    g_Bhi[idx] = hb;
    g_Blo[idx] = __float2bfloat16(b - __bfloat162float(hb));
}

// ---------------------------------------------------------------------------
// Tensor-core GEMM via mma.sync: C = T * Wr^T, 3-pass bf16 split FUSED per
// K-chunk (operands loaded once, 3 MMA groups). CTA tile 128x128, K-chunk 32
// (64B rows, SW64 swizzle), 2-stage cp.async (2 x 32KB), 8 warps, warp tile
// 64x32. Pass order caps live regs: hi*hi -> hi*lo -> lo*hi.
// ---------------------------------------------------------------------------
#define SWZ64(o) ((o) ^ (((o) >> 3) & 0x30))
#define STAGEB 32768                  // Ahi|Alo|Bhi|Blo, 8KB each
#define GSMEM  (2 * STAGEB)
#define NCHUNK 16                     // 512 / 32

__device__ __forceinline__ uint32_t smem_u32(const void* p) {
    uint32_t a;
    asm("{ .reg .u64 t; cvta.to.shared.u64 t, %1; cvt.u32.u64 %0, t; }"
        : "=r"(a) : "l"(p));
    return a;
}
__device__ __forceinline__ void cp16(uint32_t s, const void* g) {
    asm volatile("cp.async.cg.shared.global [%0], [%1], 16;" :: "r"(s), "l"(g));
}
__device__ __forceinline__ void ldm_x4(uint32_t& r0, uint32_t& r1,
                                       uint32_t& r2, uint32_t& r3, uint32_t a) {
    asm volatile("ldmatrix.sync.aligned.m8n8.x4.shared.b16 {%0,%1,%2,%3}, [%4];"
                 : "=r"(r0), "=r"(r1), "=r"(r2), "=r"(r3) : "r"(a));
}
__device__ __forceinline__ void mma_bf16(float& d0, float& d1, float& d2, float& d3,
                                         uint32_t a0, uint32_t a1, uint32_t a2,
                                         uint32_t a3, uint32_t b0, uint32_t b1) {
    asm volatile(
        "mma.sync.aligned.m16n8k16.row.col.f32.bf16.bf16.f32 "
        "{%0,%1,%2,%3}, {%4,%5,%6,%7}, {%8,%9}, {%0,%1,%2,%3};"
        : "+f"(d0), "+f"(d1), "+f"(d2), "+f"(d3)
        : "r"(a0), "r"(a1), "r"(a2), "r"(a3), "r"(b0), "r"(b1));
}

__global__ __launch_bounds__(256, 2) void k_gemm_mma(float* __restrict__ C) {
    extern __shared__ char smem[];
    const uint32_t sb = smem_u32(smem);
    const int tid  = threadIdx.x;
    const int wid  = tid >> 5, lane = tid & 31;
    const int n0   = blockIdx.y * 128;   // C rows  (A = T rows)
    const int m0   = blockIdx.x * 128;   // C cols  (B = Wr rows)
    const int wm   = (wid >> 2) * 64;    // warp row offset in tile
    const int wn   = (wid & 3) * 32;     // warp col offset in tile

    float acc[4][4][4];
#pragma unroll
    for (int i = 0; i < 4; ++i)
#pragma unroll
        for (int j = 0; j < 4; ++j)
#pragma unroll
            for (int q = 0; q < 4; ++q) acc[i][j][q] = 0.0f;

    const __nv_bfloat16* base0 = g_Ahi + (size_t)n0 * RPAD;
    const __nv_bfloat16* base1 = g_Alo + (size_t)n0 * RPAD;
    const __nv_bfloat16* base2 = g_Bhi + (size_t)m0 * RPAD;
    const __nv_bfloat16* base3 = g_Blo + (size_t)m0 * RPAD;

    // one chunk = 4 arrays x 128 rows x 64B = 2048 16B units, 8 per thread
    auto load_chunk = [&](int c, int stage) {
        const int k0 = c * 32;
        const uint32_t stb = sb + stage * STAGEB;
#pragma unroll
        for (int i = 0; i < 8; ++i) {
            int u   = tid + i * 256;
            int arr = u >> 9, rem = u & 511;
            int row = rem >> 2, cq = rem & 3;
            const __nv_bfloat16* gp =
                (arr == 0 ? base0 : arr == 1 ? base1 : arr == 2 ? base2 : base3)
                + (size_t)row * RPAD + k0 + cq * 8;
            cp16(stb + arr * 8192 + SWZ64(row * 64 + cq * 16), gp);
        }
        asm volatile("cp.async.commit_group;" ::: "memory");
    };

    load_chunk(0, 0);
    load_chunk(1, 1);

    for (int c = 0; c < NCHUNK; ++c) {
        const int stage = c & 1;
        if (c < NCHUNK - 1) asm volatile("cp.async.wait_group 1;" ::: "memory");
        else                asm volatile("cp.async.wait_group 0;" ::: "memory");
        __syncthreads();

        const uint32_t sAh = sb + stage * STAGEB;
        const uint32_t sAl = sAh + 8192;
        const uint32_t sBh = sAh + 16384;
        const uint32_t sBl = sAh + 24576;

        // precomputed per-lane address offsets (row*64 + col within array)
        const int arow = (lane & 15) * 64 + (lane >> 4) * 16;        // A frag
        const int brow = (((lane >> 4) & 1) * 8 + (lane & 7)) * 64
                       + ((lane >> 3) & 1) * 16;                      // B frag

#pragma unroll
        for (int ks = 0; ks < 2; ++ks) {         // two k16 steps in chunk
            const int kb = ks * 32;

            uint32_t ah[4][4];
#pragma unroll
            for (int mi = 0; mi < 4; ++mi)
                ldm_x4(ah[mi][0], ah[mi][1], ah[mi][2], ah[mi][3],
                       sAh + SWZ64((wm + mi * 16) * 64 + kb + arow));
            uint32_t bh[2][4];
#pragma unroll
            for (int nq = 0; nq < 2; ++nq)
                ldm_x4(bh[nq][0], bh[nq][1], bh[nq][2], bh[nq][3],
                       sBh + SWZ64((wn + nq * 16) * 64 + kb + brow));
            // pass 0: Ahi * Bhi
#pragma unroll
            for (int mi = 0; mi < 4; ++mi)
#pragma unroll
                for (int nj = 0; nj < 4; ++nj)
                    mma_bf16(acc[mi][nj][0], acc[mi][nj][1],
                             acc[mi][nj][2], acc[mi][nj][3],
                             ah[mi][0], ah[mi][1], ah[mi][2], ah[mi][3],
                             bh[nj >> 1][2 * (nj & 1)], bh[nj >> 1][2 * (nj & 1) + 1]);
            // pass 1: Ahi * Blo
            {
                uint32_t bl[2][4];
#pragma unroll
                for (int nq = 0; nq < 2; ++nq)
                    ldm_x4(bl[nq][0], bl[nq][1], bl[nq][2], bl[nq][3],
                           sBl + SWZ64((wn + nq * 16) * 64 + kb + brow));
#pragma unroll
                for (int mi = 0; mi < 4; ++mi)
#pragma unroll
                    for (int nj = 0; nj < 4; ++nj)
                        mma_bf16(acc[mi][nj][0], acc[mi][nj][1],
                                 acc[mi][nj][2], acc[mi][nj][3],
                                 ah[mi][0], ah[mi][1], ah[mi][2], ah[mi][3],
                                 bl[nj >> 1][2 * (nj & 1)], bl[nj >> 1][2 * (nj & 1) + 1]);
            }
            // pass 2: Alo * Bhi  (reuse bh, overwrite ah with lo)
            {
                uint32_t al[4][4];
#pragma unroll
                for (int mi = 0; mi < 4; ++mi)
                    ldm_x4(al[mi][0], al[mi][1], al[mi][2], al[mi][3],
                           sAl + SWZ64((wm + mi * 16) * 64 + kb + arow));
#pragma unroll
                for (int mi = 0; mi < 4; ++mi)
#pragma unroll
                    for (int nj = 0; nj < 4; ++nj)
                        mma_bf16(acc[mi][nj][0], acc[mi][nj][1],
                                 acc[mi][nj][2], acc[mi][nj][3],
                                 al[mi][0], al[mi][1], al[mi][2], al[mi][3],
                                 bh[nj >> 1][2 * (nj & 1)], bh[nj >> 1][2 * (nj & 1) + 1]);
            }
        }

        __syncthreads();                        // all reads of this stage done
        if (c + 2 < NCHUNK) load_chunk(c + 2, stage);
    }

    // Epilogue
#pragma unroll
    for (int mi = 0; mi < 4; ++mi) {
        int row = n0 + wm + mi * 16 + (lane >> 2);
#pragma unroll
        for (int nj = 0; nj < 4; ++nj) {
            int col = m0 + wn + nj * 8 + (lane & 3) * 2;
            float2* p0 = (float2*)(C + (size_t)row * NN + col);
            float2* p1 = (float2*)(C + (size_t)(row + 8) * NN + col);
            *p0 = make_float2(acc[mi][nj][0], acc[mi][nj][1]);
            *p1 = make_float2(acc[mi][nj][2], acc[mi][nj][3]);
        }
    }
}

// ---------------------------------------------------------------------------
extern "C" void kernel_launch(void* const* d_in, const int* in_sizes, int n_in,
                              void* d_out, int out_size) {
    const float* img = (const float*)d_in[0];
    const float* xc  = (const float*)d_in[1];
    const float* xr  = (const float*)d_in[2];
    float* out = (float*)d_out;

    (void)in_sizes; (void)n_in; (void)out_size;

    cudaFuncSetAttribute(k_gemm_mma, cudaFuncAttributeMaxDynamicSharedMemorySize,
                         GSMEM);

    // 1. factors
    k_compute_w<<<(NN * RPAD) / 256, 256>>>(xc, xr);
    // 2. nearest indices
    k_compute_idx<<<2, 256>>>(xc, xr);

    // 3. per-level D and T blocks (sequential: U depends on previous T)
    static const int offs[NLEV] = {0, 17, 50, 115, 244};
    static const int Ks[NLEV]   = {17, 33, 65, 129, 257};
    for (int l = 0; l < NLEV; ++l) {
        dim3 gD((Ks[l] + 255) / 256, Ks[l]);
        k_compute_D<<<gD, 256>>>(img, offs[l], Ks[l], l > 0 ? 1 : 0);
        dim3 bT(64, 4), gT((Ks[l] + 63) / 64, NN / 4);
        k_compute_T<<<gT, bT>>>(offs[l], Ks[l]);
    }

    // 4. bf16 hi/lo split of T and Wr
    k_split<<<(NN * RPAD) / 256, 256>>>();

    // 5. out = T * Wr^T on tensor cores (fused 3-pass bf16 split)
    dim3 gg(NN / 128, NN / 128);   // (32, 32)
    k_gemm_mma<<<gg, 256, GSMEM>>>(out);
}

// round 10
// speedup vs baseline: 2.4347x; 1.5100x over previous
#include <cuda_runtime.h>
#include <cuda_bf16.h>
#include <math.h>
#include <stdint.h>

#define NN   4096
#define RTOT 501
#define RPAD 512
#define NLEV 5

// ---- device scratch (static allocation: allowed) ----
__device__ float g_Wc[NN * RPAD];   // phi/psi factors for xc (rows) : [n][r]
__device__ float g_Wr[NN * RPAD];   // factors for xr (cols)         : [m][r]
__device__ float g_T [NN * RPAD];   // T = Wc * blockdiag(D)         : [n][r]
__device__ int   g_ic[RTOT];
__device__ int   g_ir[RTOT];
__device__ float g_D [257 * 257];   // current level's D
// tf32-rounded GEMM operands (bit patterns stored as float)
__device__ __align__(1024) float g_Atf[NN * RPAD];
__device__ __align__(1024) float g_Btf[NN * RPAD];

// ---------------------------------------------------------------------------
// phi(a) = sin(pi a) * exp(-a^2/20.48) / (pi a), phi(0)=1.
// EXACT zero for |a| > 28 (exp factor < 2e-17) — the GEMM k-window relies on it.
// ---------------------------------------------------------------------------
__device__ __forceinline__ float phi_f(float a) {
    float t = 3.14159265358979323846f * a;
    if (t == 0.0f) return 1.0f;
    float a2 = a * a;
    if (a2 > 784.0f) return 0.0f;
    return __fdividef(sinpif(a), t) * __expf(a2 * (-1.0f / 20.48f));
}

__device__ __forceinline__ void col_to_level(int col, int& off, int& s) {
    if (col < 17)       { off = 0;   s = 8;   }
    else if (col < 50)  { off = 17;  s = 16;  }
    else if (col < 115) { off = 50;  s = 32;  }
    else if (col < 244) { off = 115; s = 64;  }
    else                { off = 244; s = 128; }
}

__global__ void k_compute_w(const float* __restrict__ xc,
                            const float* __restrict__ xr) {
    int idx = blockIdx.x * blockDim.x + threadIdx.x;
    if (idx >= NN * RPAD) return;
    int n   = idx >> 9;
    int col = idx & (RPAD - 1);
    if (col >= RTOT) {
        g_Wc[idx] = 0.0f; g_Wr[idx] = 0.0f; g_T[idx] = 0.0f;
        return;
    }
    int off, s;
    col_to_level(col, off, s);
    int m = (col - off) - s;
    float fs = (float)s, fm = (float)m;
    g_Wc[idx] = phi_f(fs * xc[n] - fm);
    g_Wr[idx] = phi_f(fs * xr[n] - fm);
}

__device__ __forceinline__ int nearest_sorted(const float* __restrict__ x, float tgt) {
    int lo = 0, hi = NN;
    while (lo < hi) { int mid = (lo + hi) >> 1; if (x[mid] < tgt) lo = mid + 1; else hi = mid; }
    if (lo == 0)  return 0;
    if (lo == NN) return NN - 1;
    float d1 = fabsf(x[lo - 1] - tgt);
    float d2 = fabsf(x[lo] - tgt);
    return (d1 <= d2) ? (lo - 1) : lo;
}

__global__ void k_compute_idx(const float* __restrict__ xc,
                              const float* __restrict__ xr) {
    int col = blockIdx.x * blockDim.x + threadIdx.x;
    if (col >= RTOT) return;
    int off, s;
    col_to_level(col, off, s);
    int m = (col - off) - s;
    float tgt = (float)m / (float)s;
    g_ic[col] = nearest_sorted(xc, tgt);
    g_ir[col] = nearest_sorted(xr, tgt);
}

__global__ void k_compute_D(const float* __restrict__ img,
                            int off, int K, int thresh_on) {
    __shared__ float Trow[256];
    int a   = blockIdx.y;
    int b   = blockIdx.x * blockDim.x + threadIdx.x;
    int ica = g_ic[off + a];
    for (int r = threadIdx.x; r < off; r += blockDim.x)
        Trow[r] = g_T[(size_t)ica * RPAD + r];
    __syncthreads();
    if (b >= K) return;
    int irb = g_ir[off + b];
    const float* wr = &g_Wr[(size_t)irb * RPAD];
    float u = 0.0f;
    for (int r = 0; r < off; ++r) u += Trow[r] * wr[r];
    float d = img[(size_t)ica * NN + irb] - u;
    if (thresh_on && fabsf(d) <= 0.01f) d = 0.0f;
    g_D[a * K + b] = d;
}

// Windowed: Wc[n, off+a] is exactly zero outside |s*x_n - (a-s)| <= 28.
__global__ void k_compute_T(int off, int K, int s, const float* __restrict__ xc) {
    int b = blockIdx.x * blockDim.x + threadIdx.x;
    int n = blockIdx.y * blockDim.y + threadIdx.y;
    if (b >= K) return;
    float fs = (float)s, x = xc[n];
    int alo = (int)floorf(fs * x - 28.0f) + s - 1;
    int ahi = (int)ceilf (fs * x + 28.0f) + s + 1;
    if (alo < 0) alo = 0;
    if (ahi > K - 1) ahi = K - 1;
    const float* wc = &g_Wc[(size_t)n * RPAD + off];
    float acc = 0.0f;
    for (int a = alo; a <= ahi; ++a)
        acc += wc[a] * g_D[a * K + b];
    g_T[(size_t)n * RPAD + off + b] = acc;
}

// ---------------------------------------------------------------------------
// Round both GEMM operands to tf32 (stored as fp32 bit patterns)
// ---------------------------------------------------------------------------
__global__ void k_cvt() {
    int idx = blockIdx.x * blockDim.x + threadIdx.x;
    uint32_t ta, tb;
    asm("cvt.rna.tf32.f32 %0, %1;" : "=r"(ta) : "f"(g_T[idx]));
    asm("cvt.rna.tf32.f32 %0, %1;" : "=r"(tb) : "f"(g_Wr[idx]));
    g_Atf[idx] = __uint_as_float(ta);
    g_Btf[idx] = __uint_as_float(tb);
}

// ---------------------------------------------------------------------------
// tf32 GEMM with per-tile k-window: C = T * Wr^T over only the 16-col k-blocks
// where the B tile (sorted xr) can be nonzero. CTA tile 128x128, chunk K=16,
// 2-stage cp.async (2 x 16KB), 8 warps, warp tile 64x32, m16n8k8 MMAs.
// Shared layout: per row 16 floats, 4-float groups XOR-swizzled by (row>>1)&3.
// ---------------------------------------------------------------------------
#define TSTAGE 16384
#define TGSMEM (2 * TSTAGE + 256)

__device__ __forceinline__ uint32_t soff(uint32_t r, uint32_t k) {
    return r * 64 + ((((k >> 2) ^ ((r >> 1) & 3)) & 3) << 4) + ((k & 3) << 2);
}
__device__ __forceinline__ uint32_t smem_u32(const void* p) {
    uint32_t a;
    asm("{ .reg .u64 t; cvta.to.shared.u64 t, %1; cvt.u32.u64 %0, t; }"
        : "=r"(a) : "l"(p));
    return a;
}
__device__ __forceinline__ void cp16(uint32_t s, const void* g) {
    asm volatile("cp.async.cg.shared.global [%0], [%1], 16;" :: "r"(s), "l"(g));
}
__device__ __forceinline__ void mma_tf32(float& d0, float& d1, float& d2, float& d3,
                                         uint32_t a0, uint32_t a1, uint32_t a2,
                                         uint32_t a3, uint32_t b0, uint32_t b1) {
    asm volatile(
        "mma.sync.aligned.m16n8k8.row.col.f32.tf32.tf32.f32 "
        "{%0,%1,%2,%3}, {%4,%5,%6,%7}, {%8,%9}, {%0,%1,%2,%3};"
        : "+f"(d0), "+f"(d1), "+f"(d2), "+f"(d3)
        : "r"(a0), "r"(a1), "r"(a2), "r"(a3), "r"(b0), "r"(b1));
}

__global__ __launch_bounds__(256, 2) void k_gemm_tf32(float* __restrict__ C,
                                                      const float* __restrict__ xr) {
    extern __shared__ char smem[];
    const uint32_t sb = smem_u32(smem);
    int* s_list = (int*)(smem + 2 * TSTAGE);
    const int tid  = threadIdx.x;
    const int wid  = tid >> 5, lane = tid & 31;
    const int n0   = blockIdx.y * 128;   // C rows  (A = T rows)
    const int m0   = blockIdx.x * 128;   // C cols  (B = Wr rows)
    const int wm   = (wid >> 2) * 64;
    const int wn   = (wid & 3) * 32;

    // ---- active k-block list from the B tile's xr range (exact) ----
    if (tid == 0) {
        float xmin = xr[m0], xmax = xr[m0 + 127];
        const int off[5] = {0, 17, 50, 115, 244};
        const int sl[5]  = {8, 16, 32, 64, 128};
        const int kl[5]  = {17, 33, 65, 129, 257};
        uint32_t mask = 0;
#pragma unroll
        for (int l = 0; l < 5; ++l) {
            float fs = (float)sl[l];
            int lo = off[l] + sl[l] + (int)floorf(fs * xmin - 28.0f) - 1;
            int hi = off[l] + sl[l] + (int)ceilf (fs * xmax + 28.0f) + 1;
            if (lo < off[l]) lo = off[l];
            if (hi > off[l] + kl[l] - 1) hi = off[l] + kl[l] - 1;
            if (lo > hi) continue;
            for (int b = (lo >> 4); b <= (hi >> 4); ++b) mask |= (1u << b);
        }
        int nb = 0;
        while (mask) { int b = __ffs(mask) - 1; mask &= mask - 1; s_list[1 + nb++] = b; }
        s_list[0] = nb;
    }
    __syncthreads();
    const int nb = s_list[0];       // >= 2 always (level 0 spans blocks 0,1)

    float acc[4][4][4];
#pragma unroll
    for (int i = 0; i < 4; ++i)
#pragma unroll
        for (int j = 0; j < 4; ++j)
#pragma unroll
            for (int q = 0; q < 4; ++q) acc[i][j][q] = 0.0f;

    const float* Ab = g_Atf + (size_t)n0 * RPAD;
    const float* Bb = g_Btf + (size_t)m0 * RPAD;

    auto load_chunk = [&](int blk, int stage) {
        const int k0 = blk * 16;
        const uint32_t stb = sb + stage * TSTAGE;
#pragma unroll
        for (int i = 0; i < 4; ++i) {           // 1024 16B units / 256 thr
            int u   = tid + i * 256;
            int arr = u >> 9, rem = u & 511;
            int row = rem >> 2, cq = rem & 3;
            const float* gp = (arr ? Bb : Ab) + (size_t)row * RPAD + k0 + cq * 4;
            cp16(stb + arr * 8192 + row * 64 + (((cq ^ ((row >> 1) & 3)) & 3) << 4), gp);
        }
        asm volatile("cp.async.commit_group;" ::: "memory");
    };

    load_chunk(s_list[1], 0);
    load_chunk(s_list[2], 1);   // safe: nb >= 2

    const int aq = lane >> 2;         // 0..7
    const int ak = lane & 3;          // 0..3

    for (int c = 0; c < nb; ++c) {
        const int stage = c & 1;
        if (c < nb - 1) asm volatile("cp.async.wait_group 1;" ::: "memory");
        else            asm volatile("cp.async.wait_group 0;" ::: "memory");
        __syncthreads();

        const char* sA = smem + stage * TSTAGE;
        const char* sB = sA + 8192;

#pragma unroll
        for (int ks = 0; ks < 2; ++ks) {        // two k8 steps in chunk16
            const int kb = ks * 8;
            uint32_t a[4][4];
#pragma unroll
            for (int mi = 0; mi < 4; ++mi) {
                int r = wm + mi * 16 + aq;
                a[mi][0] = *(const uint32_t*)(sA + soff(r,     kb + ak));
                a[mi][1] = *(const uint32_t*)(sA + soff(r + 8, kb + ak));
                a[mi][2] = *(const uint32_t*)(sA + soff(r,     kb + ak + 4));
                a[mi][3] = *(const uint32_t*)(sA + soff(r + 8, kb + ak + 4));
            }
            uint32_t b[4][2];
#pragma unroll
            for (int nj = 0; nj < 4; ++nj) {
                int r = wn + nj * 8 + aq;
                b[nj][0] = *(const uint32_t*)(sB + soff(r, kb + ak));
                b[nj][1] = *(const uint32_t*)(sB + soff(r, kb + ak + 4));
            }
#pragma unroll
            for (int mi = 0; mi < 4; ++mi)
#pragma unroll
                for (int nj = 0; nj < 4; ++nj)
                    mma_tf32(acc[mi][nj][0], acc[mi][nj][1],
                             acc[mi][nj][2], acc[mi][nj][3],
                             a[mi][0], a[mi][1], a[mi][2], a[mi][3],
                             b[nj][0], b[nj][1]);
        }

        __syncthreads();
        if (c + 2 < nb) load_chunk(s_list[1 + c + 2], stage);
    }

    // Epilogue
#pragma unroll
    for (int mi = 0; mi < 4; ++mi) {
        int row = n0 + wm + mi * 16 + (lane >> 2);
#pragma unroll
        for (int nj = 0; nj < 4; ++nj) {
            int col = m0 + wn + nj * 8 + (lane & 3) * 2;
            float2* p0 = (float2*)(C + (size_t)row * NN + col);
            float2* p1 = (float2*)(C + (size_t)(row + 8) * NN + col);
            *p0 = make_float2(acc[mi][nj][0], acc[mi][nj][1]);
            *p1 = make_float2(acc[mi][nj][2], acc[mi][nj][3]);
        }
    }
}

// ---------------------------------------------------------------------------
extern "C" void kernel_launch(void* const* d_in, const int* in_sizes, int n_in,
                              void* d_out, int out_size) {
    const float* img = (const float*)d_in[0];
    const float* xc  = (const float*)d_in[1];
    const float* xr  = (const float*)d_in[2];
    float* out = (float*)d_out;

    (void)in_sizes; (void)n_in; (void)out_size;

    cudaFuncSetAttribute(k_gemm_tf32, cudaFuncAttributeMaxDynamicSharedMemorySize,
                         TGSMEM);

    // 1. factors
    k_compute_w<<<(NN * RPAD) / 256, 256>>>(xc, xr);
    // 2. nearest indices
    k_compute_idx<<<2, 256>>>(xc, xr);

    // 3. per-level D and T blocks (sequential: U depends on previous T)
    static const int offs[NLEV] = {0, 17, 50, 115, 244};
    static const int Ks[NLEV]   = {17, 33, 65, 129, 257};
    static const int Ss[NLEV]   = {8, 16, 32, 64, 128};
    for (int l = 0; l < NLEV; ++l) {
        dim3 gD((Ks[l] + 255) / 256, Ks[l]);
        k_compute_D<<<gD, 256>>>(img, offs[l], Ks[l], l > 0 ? 1 : 0);
        dim3 bT(64, 4), gT((Ks[l] + 63) / 64, NN / 4);
        k_compute_T<<<gT, bT>>>(offs[l], Ks[l], Ss[l], xc);
    }

    // 4. tf32 rounding of both operands
    k_cvt<<<(NN * RPAD) / 256, 256>>>();

    // 5. out = T * Wr^T, tf32 tensor cores + per-tile k-window
    dim3 gg(NN / 128, NN / 128);   // (32, 32)
    k_gemm_tf32<<<gg, 256, TGSMEM>>>(out, xr);
}

// round 11
// speedup vs baseline: 3.7531x; 1.5415x over previous
#include <cuda_runtime.h>
#include <cuda_bf16.h>
#include <math.h>
#include <stdint.h>

#define NN   4096
#define RTOT 501
#define RPAD 512
#define NLEV 5
#define CUT  20.0f              // phi exactly 0 beyond |a|>20 (exp<3e-9)

// ---- device scratch (static allocation: allowed) ----
__device__ float g_Wc[NN * RPAD];   // phi/psi factors for xc (rows) : [n][r]
__device__ float g_Wr[NN * RPAD];   // factors for xr (cols)         : [m][r]
__device__ float g_T [NN * RPAD];   // T = Wc * blockdiag(D)         : [n][r]
__device__ int   g_ic[RTOT];
__device__ int   g_ir[RTOT];
__device__ float g_D [257 * 257];   // current level's D
// tf32-rounded GEMM operands (bit patterns stored as float)
__device__ __align__(1024) float g_Atf[NN * RPAD];
__device__ __align__(1024) float g_Btf[NN * RPAD];

// ---------------------------------------------------------------------------
// phi(a) = sin(pi a) * exp(-a^2/20.48) / (pi a), phi(0)=1.
// EXACT zero for |a| > 20 — all windows below rely on it.
// ---------------------------------------------------------------------------
__device__ __forceinline__ float phi_f(float a) {
    float t = 3.14159265358979323846f * a;
    if (t == 0.0f) return 1.0f;
    float a2 = a * a;
    if (a2 > CUT * CUT) return 0.0f;
    return __fdividef(sinpif(a), t) * __expf(a2 * (-1.0f / 20.48f));
}

__device__ __forceinline__ void col_to_level(int col, int& off, int& s) {
    if (col < 17)       { off = 0;   s = 8;   }
    else if (col < 50)  { off = 17;  s = 16;  }
    else if (col < 115) { off = 50;  s = 32;  }
    else if (col < 244) { off = 115; s = 64;  }
    else                { off = 244; s = 128; }
}

__device__ __forceinline__ uint32_t to_tf32(float v) {
    uint32_t t;
    asm("cvt.rna.tf32.f32 %0, %1;" : "=r"(t) : "f"(v));
    return t;
}

// Fills Wc, Wr; writes tf32 B operand; zeroes pads of everything.
__global__ void k_compute_w(const float* __restrict__ xc,
                            const float* __restrict__ xr) {
    int idx = blockIdx.x * blockDim.x + threadIdx.x;
    if (idx >= NN * RPAD) return;
    int n   = idx >> 9;
    int col = idx & (RPAD - 1);
    if (col >= RTOT) {
        g_Wc[idx] = 0.0f; g_Wr[idx] = 0.0f; g_T[idx] = 0.0f;
        g_Atf[idx] = 0.0f; g_Btf[idx] = 0.0f;
        return;
    }
    int off, s;
    col_to_level(col, off, s);
    int m = (col - off) - s;
    float fs = (float)s, fm = (float)m;
    float wr = phi_f(fs * xr[n] - fm);
    g_Wc[idx] = phi_f(fs * xc[n] - fm);
    g_Wr[idx] = wr;
    g_Btf[idx] = __uint_as_float(to_tf32(wr));
}

__device__ __forceinline__ int nearest_sorted(const float* __restrict__ x, float tgt) {
    int lo = 0, hi = NN;
    while (lo < hi) { int mid = (lo + hi) >> 1; if (x[mid] < tgt) lo = mid + 1; else hi = mid; }
    if (lo == 0)  return 0;
    if (lo == NN) return NN - 1;
    float d1 = fabsf(x[lo - 1] - tgt);
    float d2 = fabsf(x[lo] - tgt);
    return (d1 <= d2) ? (lo - 1) : lo;
}

__global__ void k_compute_idx(const float* __restrict__ xc,
                              const float* __restrict__ xr) {
    int col = blockIdx.x * blockDim.x + threadIdx.x;
    if (col >= RTOT) return;
    int off, s;
    col_to_level(col, off, s);
    int m = (col - off) - s;
    float tgt = (float)m / (float)s;
    g_ic[col] = nearest_sorted(xc, tgt);
    g_ir[col] = nearest_sorted(xr, tgt);
}

// ---------------------------------------------------------------------------
// D[a,b] = thresh( img[ic_a, ir_b] - U ), U = sum_r T[ic_a,r]*Wr[ir_b,r].
// The r-dot is windowed per previous level: Wr[ir_b, off_l + j] is exactly
// zero outside |s_l * x - (j - s_l)| <= CUT.
// ---------------------------------------------------------------------------
__global__ void k_compute_D(const float* __restrict__ img,
                            const float* __restrict__ xr,
                            int off, int K, int thresh_on) {
    __shared__ float Trow[256];
    int a   = blockIdx.y;
    int b   = blockIdx.x * blockDim.x + threadIdx.x;
    int ica = g_ic[off + a];
    for (int r = threadIdx.x; r < off; r += blockDim.x)
        Trow[r] = g_T[(size_t)ica * RPAD + r];
    __syncthreads();
    if (b >= K) return;
    int irb = g_ir[off + b];
    const float* wr = &g_Wr[(size_t)irb * RPAD];
    float u = 0.0f;
    if (off > 0) {
        float x = xr[irb];
        const int loff[4] = {0, 17, 50, 115};
        const int lsc[4]  = {8, 16, 32, 64};
        const int lK[4]   = {17, 33, 65, 129};
#pragma unroll
        for (int l = 0; l < 4; ++l) {
            if (loff[l] >= off) break;
            float fs = (float)lsc[l];
            int jlo = (int)floorf(fs * x - CUT) + lsc[l] - 1;
            int jhi = (int)ceilf (fs * x + CUT) + lsc[l] + 1;
            if (jlo < 0) jlo = 0;
            if (jhi > lK[l] - 1) jhi = lK[l] - 1;
            int base = loff[l];
            for (int j = jlo; j <= jhi; ++j)
                u += Trow[base + j] * wr[base + j];
        }
    }
    float d = img[(size_t)ica * NN + irb] - u;
    if (thresh_on && fabsf(d) <= 0.01f) d = 0.0f;
    g_D[a * K + b] = d;
}

// Windowed over a; also emits the tf32 A operand (fused cvt).
__global__ void k_compute_T(int off, int K, int s, const float* __restrict__ xc) {
    int b = blockIdx.x * blockDim.x + threadIdx.x;
    int n = blockIdx.y * blockDim.y + threadIdx.y;
    if (b >= K) return;
    float fs = (float)s, x = xc[n];
    int alo = (int)floorf(fs * x - CUT) + s - 1;
    int ahi = (int)ceilf (fs * x + CUT) + s + 1;
    if (alo < 0) alo = 0;
    if (ahi > K - 1) ahi = K - 1;
    const float* wc = &g_Wc[(size_t)n * RPAD + off];
    float acc = 0.0f;
    for (int a = alo; a <= ahi; ++a)
        acc += wc[a] * g_D[a * K + b];
    size_t idx = (size_t)n * RPAD + off + b;
    g_T[idx] = acc;
    g_Atf[idx] = __uint_as_float(to_tf32(acc));
}

// ---------------------------------------------------------------------------
// tf32 GEMM with per-tile k-window: C = T * Wr^T over only the 16-col k-blocks
// where the B tile (sorted xr) can be nonzero. CTA tile 128x128, chunk K=16,
// 2-stage cp.async (2 x 16KB), 8 warps, warp tile 64x32, m16n8k8 MMAs.
// ---------------------------------------------------------------------------
#define TSTAGE 16384
#define TGSMEM (2 * TSTAGE + 256)

__device__ __forceinline__ uint32_t soff(uint32_t r, uint32_t k) {
    return r * 64 + ((((k >> 2) ^ ((r >> 1) & 3)) & 3) << 4) + ((k & 3) << 2);
}
__device__ __forceinline__ uint32_t smem_u32(const void* p) {
    uint32_t a;
    asm("{ .reg .u64 t; cvta.to.shared.u64 t, %1; cvt.u32.u64 %0, t; }"
        : "=r"(a) : "l"(p));
    return a;
}
__device__ __forceinline__ void cp16(uint32_t s, const void* g) {
    asm volatile("cp.async.cg.shared.global [%0], [%1], 16;" :: "r"(s), "l"(g));
}
__device__ __forceinline__ void mma_tf32(float& d0, float& d1, float& d2, float& d3,
                                         uint32_t a0, uint32_t a1, uint32_t a2,
                                         uint32_t a3, uint32_t b0, uint32_t b1) {
    asm volatile(
        "mma.sync.aligned.m16n8k8.row.col.f32.tf32.tf32.f32 "
        "{%0,%1,%2,%3}, {%4,%5,%6,%7}, {%8,%9}, {%0,%1,%2,%3};"
        : "+f"(d0), "+f"(d1), "+f"(d2), "+f"(d3)
        : "r"(a0), "r"(a1), "r"(a2), "r"(a3), "r"(b0), "r"(b1));
}

__global__ __launch_bounds__(256, 2) void k_gemm_tf32(float* __restrict__ C,
                                                      const float* __restrict__ xr) {
    extern __shared__ char smem[];
    const uint32_t sb = smem_u32(smem);
    int* s_list = (int*)(smem + 2 * TSTAGE);
    const int tid  = threadIdx.x;
    const int wid  = tid >> 5, lane = tid & 31;
    const int n0   = blockIdx.y * 128;   // C rows  (A = T rows)
    const int m0   = blockIdx.x * 128;   // C cols  (B = Wr rows)
    const int wm   = (wid >> 2) * 64;
    const int wn   = (wid & 3) * 32;

    // ---- active k-block list from the B tile's xr range (exact) ----
    if (tid == 0) {
        float xmin = xr[m0], xmax = xr[m0 + 127];
        const int off[5] = {0, 17, 50, 115, 244};
        const int sl[5]  = {8, 16, 32, 64, 128};
        const int kl[5]  = {17, 33, 65, 129, 257};
        uint32_t mask = 0;
#pragma unroll
        for (int l = 0; l < 5; ++l) {
            float fs = (float)sl[l];
            int lo = off[l] + sl[l] + (int)floorf(fs * xmin - CUT) - 1;
            int hi = off[l] + sl[l] + (int)ceilf (fs * xmax + CUT) + 1;
            if (lo < off[l]) lo = off[l];
            if (hi > off[l] + kl[l] - 1) hi = off[l] + kl[l] - 1;
            if (lo > hi) continue;
            for (int b = (lo >> 4); b <= (hi >> 4); ++b) mask |= (1u << b);
        }
        int nb = 0;
        while (mask) { int b = __ffs(mask) - 1; mask &= mask - 1; s_list[1 + nb++] = b; }
        s_list[0] = nb;
    }
    __syncthreads();
    const int nb = s_list[0];       // >= 2 always (level 0 spans blocks 0,1)

    float acc[4][4][4];
#pragma unroll
    for (int i = 0; i < 4; ++i)
#pragma unroll
        for (int j = 0; j < 4; ++j)
#pragma unroll
            for (int q = 0; q < 4; ++q) acc[i][j][q] = 0.0f;

    const float* Ab = g_Atf + (size_t)n0 * RPAD;
    const float* Bb = g_Btf + (size_t)m0 * RPAD;

    auto load_chunk = [&](int blk, int stage) {
        const int k0 = blk * 16;
        const uint32_t stb = sb + stage * TSTAGE;
#pragma unroll
        for (int i = 0; i < 4; ++i) {           // 1024 16B units / 256 thr
            int u   = tid + i * 256;
            int arr = u >> 9, rem = u & 511;
            int row = rem >> 2, cq = rem & 3;
            const float* gp = (arr ? Bb : Ab) + (size_t)row * RPAD + k0 + cq * 4;
            cp16(stb + arr * 8192 + row * 64 + (((cq ^ ((row >> 1) & 3)) & 3) << 4), gp);
        }
        asm volatile("cp.async.commit_group;" ::: "memory");
    };

    load_chunk(s_list[1], 0);
    load_chunk(s_list[2], 1);   // safe: nb >= 2

    const int aq = lane >> 2;         // 0..7
    const int ak = lane & 3;          // 0..3

    for (int c = 0; c < nb; ++c) {
        const int stage = c & 1;
        if (c < nb - 1) asm volatile("cp.async.wait_group 1;" ::: "memory");
        else            asm volatile("cp.async.wait_group 0;" ::: "memory");
        __syncthreads();

        const char* sA = smem + stage * TSTAGE;
        const char* sB = sA + 8192;

#pragma unroll
        for (int ks = 0; ks < 2; ++ks) {        // two k8 steps in chunk16
            const int kb = ks * 8;
            uint32_t a[4][4];
#pragma unroll
            for (int mi = 0; mi < 4; ++mi) {
                int r = wm + mi * 16 + aq;
                a[mi][0] = *(const uint32_t*)(sA + soff(r,     kb + ak));
                a[mi][1] = *(const uint32_t*)(sA + soff(r + 8, kb + ak));
                a[mi][2] = *(const uint32_t*)(sA + soff(r,     kb + ak + 4));
                a[mi][3] = *(const uint32_t*)(sA + soff(r + 8, kb + ak + 4));
            }
            uint32_t b[4][2];
#pragma unroll
            for (int nj = 0; nj < 4; ++nj) {
                int r = wn + nj * 8 + aq;
                b[nj][0] = *(const uint32_t*)(sB + soff(r, kb + ak));
                b[nj][1] = *(const uint32_t*)(sB + soff(r, kb + ak + 4));
            }
#pragma unroll
            for (int mi = 0; mi < 4; ++mi)
#pragma unroll
                for (int nj = 0; nj < 4; ++nj)
                    mma_tf32(acc[mi][nj][0], acc[mi][nj][1],
                             acc[mi][nj][2], acc[mi][nj][3],
                             a[mi][0], a[mi][1], a[mi][2], a[mi][3],
                             b[nj][0], b[nj][1]);
        }

        __syncthreads();
        if (c + 2 < nb) load_chunk(s_list[1 + c + 2], stage);
    }

    // Epilogue
#pragma unroll
    for (int mi = 0; mi < 4; ++mi) {
        int row = n0 + wm + mi * 16 + (lane >> 2);
#pragma unroll
        for (int nj = 0; nj < 4; ++nj) {
            int col = m0 + wn + nj * 8 + (lane & 3) * 2;
            float2* p0 = (float2*)(C + (size_t)row * NN + col);
            float2* p1 = (float2*)(C + (size_t)(row + 8) * NN + col);
            *p0 = make_float2(acc[mi][nj][0], acc[mi][nj][1]);
            *p1 = make_float2(acc[mi][nj][2], acc[mi][nj][3]);
        }
    }
}

// ---------------------------------------------------------------------------
extern "C" void kernel_launch(void* const* d_in, const int* in_sizes, int n_in,
                              void* d_out, int out_size) {
    const float* img = (const float*)d_in[0];
    const float* xc  = (const float*)d_in[1];
    const float* xr  = (const float*)d_in[2];
    float* out = (float*)d_out;

    (void)in_sizes; (void)n_in; (void)out_size;

    cudaFuncSetAttribute(k_gemm_tf32, cudaFuncAttributeMaxDynamicSharedMemorySize,
                         TGSMEM);

    // 1. factors (+ fused tf32 cvt of B)
    k_compute_w<<<(NN * RPAD) / 256, 256>>>(xc, xr);
    // 2. nearest indices
    k_compute_idx<<<2, 256>>>(xc, xr);

    // 3. per-level D and T blocks (sequential: U depends on previous T)
    static const int offs[NLEV] = {0, 17, 50, 115, 244};
    static const int Ks[NLEV]   = {17, 33, 65, 129, 257};
    static const int Ss[NLEV]   = {8, 16, 32, 64, 128};
    for (int l = 0; l < NLEV; ++l) {
        dim3 gD((Ks[l] + 255) / 256, Ks[l]);
        k_compute_D<<<gD, 256>>>(img, xr, offs[l], Ks[l], l > 0 ? 1 : 0);
        dim3 bT(64, 4), gT((Ks[l] + 63) / 64, NN / 4);
        k_compute_T<<<gT, bT>>>(offs[l], Ks[l], Ss[l], xc);
    }

    // 4. out = T * Wr^T, tf32 tensor cores + per-tile k-window
    dim3 gg(NN / 128, NN / 128);   // (32, 32)
    k_gemm_tf32<<<gg, 256, TGSMEM>>>(out, xr);
}